// round 10
// baseline (speedup 1.0000x reference)
#include <cuda_runtime.h>
#include <math_constants.h>

// ScalarDistanceDeepSet via exact piecewise-linear collapse + cell histogram.
// K1 prep (1 block): breakpoints, per-(segment,feature) (a,c) tables, clamped
//   relu crossings, sorted boundary array, dedupe (uniques+ranks), bucket index.
// K2 hist: per pair bucket -> short uniform-step search over uniques -> ONE
//   packed 64-bit atomic (cnt<<48 | q+bias). ILP-4 across rows.
// K3 pooled: warp per (batch,segment): packed scan + range algebra ->
//   fixed-point atomics; self-zeroes the hist cells for the next graph replay.
// K4 head: small MLP; self-zeroes pooled accumulators.
// All cross-block accumulation is integer => deterministic. No zero pass:
// device globals start at zero and every consumer restores zero after reading.

#define NB    32
#define NN    256
#define P1    64
#define P2    128
#define R1    256
#define R2    128
#define OD    64
#define NSEG  65
#define NCELL 129
#define NSLOT (NSEG * NCELL)      // 8385
#define NBND  (NSLOT - 1)         // 8384
#define SCALE_F    67108864.0f    // 2^26
#define INV_SCALE  (1.0 / 67108864.0)
#define PSCALE     4194304.0      // 2^22
#define INV_PSCALE (1.0 / 4194304.0)
#define QBIAS      (1LL << 29)
#define PACK_ONE   (1ULL << 48)
#define LOWMASK    ((1ULL << 48) - 1ULL)
#define NBUCK 1024
#define BLO   (-6.0f)
#define BSTEP (12.0f / 1024.0f)
#define BINV  (1024.0f / 12.0f)
#define HIST_GRID 592
#define NTASK (NB * (NN / 4))     // 2048
#define POOL_WARPS 8

__device__ float              g_bnd[NBND];
__device__ float              g_A[NSEG * P2];
__device__ float              g_Cc[NSEG * P2];
__device__ int2               g_range[NSEG * P2];
__device__ float              g_uv[NBND];           // unique sorted boundaries
__device__ unsigned short     g_pref[NBND + 1];     // first-occurrence rank
__device__ int                g_bstart[NBUCK + 1];  // count(uv < edge_k)
__device__ int                g_U;
__device__ int                g_maxw;
__device__ unsigned long long g_h[NB * NSLOT];      // packed (cnt<<48 | q+bias)
__device__ unsigned long long g_poolq[NB * P2];     // fixed-point pooled

// ---------------------------------------------------------------------------
// K1: single block, 1024 threads. Everything before the histogram.
// ---------------------------------------------------------------------------
#define DCH 9   // 1024*9 >= 8384
__global__ void __launch_bounds__(1024)
prep_kernel(const float* __restrict__ W1, const float* __restrict__ b1,
            const float* __restrict__ W2, const float* __restrict__ b2) {
    __shared__ float sth[NSEG * P2];   // 33.3 KB thetas
    __shared__ float sw[P1], sbb[P1], stk[P1], sts[P1];
    __shared__ int   srk[P1];
    __shared__ int   sc[1024];
    int t = threadIdx.x;

    // breakpoints + stable ranks
    if (t < P1) {
        float w = W1[t], b = b1[t];
        sw[t] = w; sbb[t] = b;
        stk[t] = (w != 0.0f) ? (-b / w) : CUDART_INF_F;
    }
    __syncthreads();
    if (t < P1) {
        float tkv = stk[t];
        int r = 0;
        for (int kk = 0; kk < P1; kk++) {
            float tv = stk[kk];
            if (tv < tkv || (tv == tkv && kk < t)) r++;
        }
        srk[t] = r;
        sts[r] = tkv;
    }
    __syncthreads();

    // per-(m,f) tables + clamped theta
    for (int it = t; it < NSEG * P2; it += 1024) {
        int m = it >> 7, f = it & 127;
        float a = 0.0f, c = b2[f];
        for (int k = 0; k < P1; k++) {
            float w = sw[k], b = sbb[k];
            int r = srk[k];
            bool active = (w > 0.0f) ? (m > r)
                        : (w < 0.0f) ? (m <= r)
                        : (b > 0.0f);
            if (active) {
                float w2 = W2[k * P2 + f];
                a = fmaf(w, w2, a);
                c = fmaf(b, w2, c);
            }
        }
        g_A[it] = a; g_Cc[it] = c;

        float lo_t = (m == 0)        ? -CUDART_INF_F : sts[m - 1];
        float hi_t = (m == NSEG - 1) ?  CUDART_INF_F : sts[m];
        float th;
        if (a != 0.0f) th = fminf(fmaxf(-c / a, lo_t), hi_t);
        else           th = lo_t;
        sth[it] = th;
    }
    __syncthreads();

    // intra-segment theta ranks -> g_bnd + active ranges
    for (int it = t; it < NSEG * P2; it += 1024) {
        int m = it >> 7, f = it & 127;
        float a = g_A[it], c = g_Cc[it];
        float th = sth[it];
        const float* seg = sth + (m << 7);
        int p = 0;
        for (int k = 0; k < P2; k++) {
            float tv = seg[k];
            if (tv < th || (tv == th && k < f)) p++;
        }
        g_bnd[m * NCELL + p] = th;
        if (f == 0 && m < NSEG - 1) g_bnd[m * NCELL + P2] = sts[m];
        int rlo, rhi;
        if (a > 0.0f)      { rlo = p + 1; rhi = NCELL; }
        else if (a < 0.0f) { rlo = 0;     rhi = p + 1; }
        else               { rlo = 0;     rhi = (c > 0.0f) ? NCELL : 0; }
        g_range[it] = make_int2(rlo, rhi);
    }
    __syncthreads();   // g_bnd complete (block-wide global visibility)

    // dedupe: heads + block scan -> uniques + first-occurrence ranks
    int i0 = t * DCH;
    int heads[DCH]; int cnt = 0;
    #pragma unroll
    for (int e = 0; e < DCH; e++) {
        int i = i0 + e; int h = 0;
        if (i < NBND) h = (i == 0) || (g_bnd[i] != g_bnd[i - 1]);
        heads[e] = h; cnt += h;
    }
    sc[t] = cnt; __syncthreads();
    for (int off = 1; off < 1024; off <<= 1) {
        int v = sc[t]; if (t >= off) v += sc[t - off];
        __syncthreads(); sc[t] = v; __syncthreads();
    }
    int excl = sc[t] - cnt;
    int U = sc[1023];
    int u = excl;
    #pragma unroll
    for (int e = 0; e < DCH; e++) {
        int i = i0 + e;
        if (heads[e]) { g_uv[u] = g_bnd[i]; g_pref[u] = (unsigned short)i; u++; }
    }
    if (t == 0) { g_pref[U] = (unsigned short)NBND; g_U = U; }
    __syncthreads();

    // bucket table
    for (int k = t; k <= NBUCK; k += 1024) {
        float edge = fmaf((float)k, BSTEP, BLO);
        int pos = 0, n = U;
        while (n > 0) {
            int half = n >> 1, mid = pos + half;
            if (g_uv[mid] < edge) { pos = mid + 1; n -= half + 1; }
            else                  { n = half; }
        }
        g_bstart[k] = pos;
    }
    __syncthreads();

    // widened max bucket width (must match hist's lo/hi formula)
    int lmax = 0;
    for (int k = t; k < NBUCK; k += 1024) {
        int lo = (k == 0)         ? 0 : g_bstart[k - 1];
        int hi = (k >= NBUCK - 1) ? U : g_bstart[k + 2];
        lmax = max(lmax, hi - lo);
    }
    sc[t] = lmax; __syncthreads();
    for (int off = 512; off > 0; off >>= 1) {
        if (t < off) sc[t] = max(sc[t], sc[t + off]);
        __syncthreads();
    }
    if (t == 0) g_maxw = sc[0];
}

// ---------------------------------------------------------------------------
// K2: histogram (unchanged from R9).
// ---------------------------------------------------------------------------
#define HIST_SMEM (NBND * 4 + (NBND + 2) * 2 + (NBUCK + 1) * 4)   // 54408 B

__global__ void __launch_bounds__(256)
hist_kernel(const float* __restrict__ dm, const int* __restrict__ lengths) {
    extern __shared__ char dyn[];
    float*          suv   = (float*)dyn;                               // [U]
    unsigned short* spref = (unsigned short*)(dyn + NBND * 4);         // [U+1]
    int*            sbst  = (int*)(dyn + NBND * 4 + (NBND + 2) * 2);   // [NBUCK+1]
    int tid = threadIdx.x;

    int U    = g_U;
    int maxw = g_maxw;
    int steps = (maxw > 0) ? (32 - __clz(maxw)) : 0;   // block-uniform

    for (int i = tid; i < U;       i += 256) suv[i]   = g_uv[i];
    for (int i = tid; i <= U;      i += 256) spref[i] = g_pref[i];
    for (int i = tid; i <= NBUCK;  i += 256) sbst[i]  = g_bstart[i];
    __syncthreads();

    for (int task = blockIdx.x; task < NTASK; task += gridDim.x) {
        int b  = task & 31;
        int i0 = (task >> 5) << 2;
        int L  = __ldg(lengths + b);
        if (i0 >= L - 1) continue;

        const float* rowp = dm + ((size_t)b << 16) + ((size_t)i0 << 8) + tid;
        float s[4]; int n[4], pos[4];
        #pragma unroll
        for (int r = 0; r < 4; r++) {
            int i = i0 + r;
            bool valid = (i < L - 1) && (tid > i) && (tid < L);
            float sv = valid ? rowp[r << 8] : 0.0f;
            s[r] = sv;
            int ib = __float2int_rd((sv - BLO) * BINV);
            ib = min(max(ib, 0), NBUCK - 1);
            int lo = (ib == 0)         ? 0 : sbst[ib - 1];
            int hi = (ib >= NBUCK - 1) ? U : sbst[ib + 2];
            pos[r] = lo;
            n[r]   = valid ? (hi - lo) : 0;
        }
        for (int it = 0; it < steps; it++) {
            #pragma unroll
            for (int r = 0; r < 4; r++) {
                if (n[r] > 0) {
                    int half = n[r] >> 1;
                    int mid  = pos[r] + half;
                    if (suv[mid] < s[r]) { pos[r] = mid + 1; n[r] -= half + 1; }
                    else                 { n[r] = half; }
                }
            }
        }
        unsigned long long* hb = g_h + (size_t)b * NSLOT;
        #pragma unroll
        for (int r = 0; r < 4; r++) {
            int i = i0 + r;
            bool valid = (i < L - 1) && (tid > i) && (tid < L);
            if (valid) {
                int pO = spref[pos[r]];
                long long q = (long long)llrintf(s[r] * SCALE_F) + QBIAS;
                atomicAdd(&hb[pO], PACK_ONE + (unsigned long long)q);
            }
        }
    }
}

// ---------------------------------------------------------------------------
// K3: pooled. 1 warp per (batch, segment). Packed 129-cell scan via shuffles,
// range algebra, fixed-point atomics. Self-zeroes each hist cell after read.
// ---------------------------------------------------------------------------
__global__ void __launch_bounds__(POOL_WARPS * 32)
pooled_kernel() {
    __shared__ unsigned long long ps[POOL_WARPS][130];
    int tid = threadIdx.x, warp = tid >> 5, lane = tid & 31;
    int u = blockIdx.x * POOL_WARPS + warp;
    if (u >= NSEG * NB) return;
    int m = u % NSEG;
    int b = u / NSEG;

    unsigned long long* h = g_h + (size_t)b * NSLOT + m * NCELL;
    int base = lane * 4;
    int ncl  = (lane == 31) ? 5 : 4;
    unsigned long long ls[5];
    unsigned long long run = 0ULL;
    #pragma unroll
    for (int e = 0; e < 5; e++) {
        if (e < ncl) {
            ls[e] = run;
            run += __ldcg(h + base + e);
        }
    }
    #pragma unroll
    for (int e = 0; e < 5; e++) {       // restore zero for next graph replay
        if (e < ncl) h[base + e] = 0ULL;
    }
    unsigned long long inc = run;
    #pragma unroll
    for (int off = 1; off < 32; off <<= 1) {
        unsigned long long v = __shfl_up_sync(0xffffffffu, inc, off);
        if (lane >= off) inc += v;
    }
    unsigned long long ex = inc - run;
    #pragma unroll
    for (int e = 0; e < 5; e++) {
        if (e < ncl) ps[warp][base + e] = ex + ls[e];
    }
    if (lane == 31) ps[warp][NCELL] = inc;
    __syncwarp();

    #pragma unroll
    for (int ff = 0; ff < 4; ff++) {
        int f = lane + 32 * ff;
        int idx = m * P2 + f;
        float a = g_A[idx], c = g_Cc[idx];
        int2 rg = g_range[idx];
        unsigned long long dv = ps[warp][rg.y] - ps[warp][rg.x];
        int cnt = (int)(dv >> 48);
        long long sumq = (long long)(dv & LOWMASK) - ((long long)cnt << 29);
        float val = a * (float)((double)sumq * INV_SCALE) + c * (float)cnt;
        long long qq = llrint((double)val * PSCALE);
        atomicAdd(&g_poolq[b * P2 + f], (unsigned long long)qq);
    }
}

// ---------------------------------------------------------------------------
// K4: head. grid NB, 512 threads. Self-zeroes g_poolq after reading.
// ---------------------------------------------------------------------------
__global__ void __launch_bounds__(512)
head_kernel(const float* __restrict__ W3, const float* __restrict__ b3,
            const float* __restrict__ W4, const float* __restrict__ b4,
            const float* __restrict__ W5, const float* __restrict__ b5,
            float* __restrict__ out) {
    __shared__ float pooled[P2];
    __shared__ float r1v[R1];
    __shared__ float r2v[R2];
    __shared__ float part[512];
    int b = blockIdx.x, t = threadIdx.x;

    if (t < P2) {
        pooled[t] = (float)((double)(long long)g_poolq[b * P2 + t] * INV_PSCALE);
        g_poolq[b * P2 + t] = 0ULL;     // restore zero for next graph replay
    }
    __syncthreads();

    {   // layer1: 256 outputs, 2-way K split (K=128)
        int o = t & 255, h = t >> 8;
        float v = 0.0f;
        int k0 = h * 64;
        #pragma unroll
        for (int k = 0; k < 64; k++)
            v = fmaf(pooled[k0 + k], W3[(k0 + k) * R1 + o], v);
        part[t] = v;
    }
    __syncthreads();
    if (t < R1)
        r1v[t] = fmaxf(b3[t] + part[t] + part[t + 256], 0.0f);
    __syncthreads();

    {   // layer2: 128 outputs, 4-way K split (K=256)
        int o = t & 127, ch = t >> 7;
        float v = 0.0f;
        int k0 = ch * 64;
        #pragma unroll
        for (int k = 0; k < 64; k++)
            v = fmaf(r1v[k0 + k], W4[(k0 + k) * R2 + o], v);
        __syncthreads();
        part[t] = v;
    }
    __syncthreads();
    if (t < R2) {
        float v = b4[t];
        #pragma unroll
        for (int j = 0; j < 4; j++) v += part[t + 128 * j];
        r2v[t] = fmaxf(v, 0.0f);
    }
    __syncthreads();

    {   // layer3: 64 outputs, 8-way K split (K=128)
        int o = t & 63, ch = t >> 6;
        float v = 0.0f;
        int k0 = ch * 16;
        #pragma unroll
        for (int k = 0; k < 16; k++)
            v = fmaf(r2v[k0 + k], W5[(k0 + k) * OD + o], v);
        __syncthreads();
        part[t] = v;
    }
    __syncthreads();
    if (t < OD) {
        float v = b5[t];
        #pragma unroll
        for (int j = 0; j < 8; j++) v += part[t + 64 * j];
        out[b * OD + t] = v;
    }
}

// ---------------------------------------------------------------------------
extern "C" void kernel_launch(void* const* d_in, const int* in_sizes, int n_in,
                              void* d_out, int out_size) {
    const float* dm      = (const float*)d_in[0];
    const int*   lengths = (const int*)  d_in[1];
    const float* W1 = (const float*)d_in[2],  *b1 = (const float*)d_in[3];
    const float* W2 = (const float*)d_in[4],  *b2 = (const float*)d_in[5];
    const float* W3 = (const float*)d_in[6],  *b3 = (const float*)d_in[7];
    const float* W4 = (const float*)d_in[8],  *b4 = (const float*)d_in[9];
    const float* W5 = (const float*)d_in[10], *b5 = (const float*)d_in[11];
    float* out = (float*)d_out;

    cudaFuncSetAttribute((const void*)hist_kernel,
                         cudaFuncAttributeMaxDynamicSharedMemorySize, HIST_SMEM);

    const int pool_grid = (NSEG * NB + POOL_WARPS - 1) / POOL_WARPS;  // 260

    prep_kernel<<<1, 1024>>>(W1, b1, W2, b2);
    hist_kernel<<<HIST_GRID, 256, HIST_SMEM>>>(dm, lengths);
    pooled_kernel<<<pool_grid, POOL_WARPS * 32>>>();
    head_kernel<<<NB, 512>>>(W3, b3, W4, b4, W5, b5, out);
}

// round 11
// speedup vs baseline: 1.0054x; 1.0054x over previous
#include <cuda_runtime.h>
#include <math_constants.h>

// ScalarDistanceDeepSet via exact piecewise-linear collapse + cell histogram.
// K1 prep (1 block): breakpoints, per-(segment,feature) (a,c) tables, clamped
//   relu crossings, sorted boundary array, dedupe (uniques+ranks), bucket index.
// K2 hist: per pair bucket -> short uniform-step search over uniques -> ONE
//   packed 64-bit atomic (cnt<<48 | q+bias). ILP-4 across rows.
// K3 pooled: warp per (batch,segment): packed scan + range algebra ->
//   fixed-point atomics; self-zeroes the hist cells for the next graph replay.
// K4 head: small MLP; self-zeroes pooled accumulators.
// All cross-block accumulation is integer => deterministic. No zero pass:
// device globals start at zero and every consumer restores zero after reading.

#define NB    32
#define NN    256
#define P1    64
#define P2    128
#define R1    256
#define R2    128
#define OD    64
#define NSEG  65
#define NCELL 129
#define NSLOT (NSEG * NCELL)      // 8385
#define NBND  (NSLOT - 1)         // 8384
#define SCALE_F    67108864.0f    // 2^26
#define INV_SCALE  (1.0 / 67108864.0)
#define PSCALE     4194304.0      // 2^22
#define INV_PSCALE (1.0 / 4194304.0)
#define QBIAS      (1LL << 29)
#define PACK_ONE   (1ULL << 48)
#define LOWMASK    ((1ULL << 48) - 1ULL)
#define NBUCK 1024
#define BLO   (-6.0f)
#define BSTEP (12.0f / 1024.0f)
#define BINV  (1024.0f / 12.0f)
#define HIST_GRID 592
#define NTASK (NB * (NN / 4))     // 2048
#define POOL_WARPS 8

__device__ float              g_bnd[NBND];
__device__ float              g_A[NSEG * P2];
__device__ float              g_Cc[NSEG * P2];
__device__ int2               g_range[NSEG * P2];
__device__ float              g_uv[NBND];           // unique sorted boundaries
__device__ unsigned short     g_pref[NBND + 1];     // first-occurrence rank
__device__ int                g_bstart[NBUCK + 1];  // count(uv < edge_k)
__device__ int                g_U;
__device__ int                g_maxw;
__device__ unsigned long long g_h[NB * NSLOT];      // packed (cnt<<48 | q+bias)
__device__ unsigned long long g_poolq[NB * P2];     // fixed-point pooled

// ---------------------------------------------------------------------------
// K1: single block, 1024 threads. Everything before the histogram.
// ---------------------------------------------------------------------------
#define DCH 9   // 1024*9 >= 8384
__global__ void __launch_bounds__(1024)
prep_kernel(const float* __restrict__ W1, const float* __restrict__ b1,
            const float* __restrict__ W2, const float* __restrict__ b2) {
    __shared__ float sth[NSEG * P2];   // 33.3 KB thetas
    __shared__ float sw[P1], sbb[P1], stk[P1], sts[P1];
    __shared__ int   srk[P1];
    __shared__ int   sc[1024];
    int t = threadIdx.x;

    // breakpoints + stable ranks
    if (t < P1) {
        float w = W1[t], b = b1[t];
        sw[t] = w; sbb[t] = b;
        stk[t] = (w != 0.0f) ? (-b / w) : CUDART_INF_F;
    }
    __syncthreads();
    if (t < P1) {
        float tkv = stk[t];
        int r = 0;
        for (int kk = 0; kk < P1; kk++) {
            float tv = stk[kk];
            if (tv < tkv || (tv == tkv && kk < t)) r++;
        }
        srk[t] = r;
        sts[r] = tkv;
    }
    __syncthreads();

    // per-(m,f) tables + clamped theta
    for (int it = t; it < NSEG * P2; it += 1024) {
        int m = it >> 7, f = it & 127;
        float a = 0.0f, c = b2[f];
        for (int k = 0; k < P1; k++) {
            float w = sw[k], b = sbb[k];
            int r = srk[k];
            bool active = (w > 0.0f) ? (m > r)
                        : (w < 0.0f) ? (m <= r)
                        : (b > 0.0f);
            if (active) {
                float w2 = W2[k * P2 + f];
                a = fmaf(w, w2, a);
                c = fmaf(b, w2, c);
            }
        }
        g_A[it] = a; g_Cc[it] = c;

        float lo_t = (m == 0)        ? -CUDART_INF_F : sts[m - 1];
        float hi_t = (m == NSEG - 1) ?  CUDART_INF_F : sts[m];
        float th;
        if (a != 0.0f) th = fminf(fmaxf(-c / a, lo_t), hi_t);
        else           th = lo_t;
        sth[it] = th;
    }
    __syncthreads();

    // intra-segment theta ranks -> g_bnd + active ranges
    for (int it = t; it < NSEG * P2; it += 1024) {
        int m = it >> 7, f = it & 127;
        float a = g_A[it], c = g_Cc[it];
        float th = sth[it];
        const float* seg = sth + (m << 7);
        int p = 0;
        for (int k = 0; k < P2; k++) {
            float tv = seg[k];
            if (tv < th || (tv == th && k < f)) p++;
        }
        g_bnd[m * NCELL + p] = th;
        if (f == 0 && m < NSEG - 1) g_bnd[m * NCELL + P2] = sts[m];
        int rlo, rhi;
        if (a > 0.0f)      { rlo = p + 1; rhi = NCELL; }
        else if (a < 0.0f) { rlo = 0;     rhi = p + 1; }
        else               { rlo = 0;     rhi = (c > 0.0f) ? NCELL : 0; }
        g_range[it] = make_int2(rlo, rhi);
    }
    __syncthreads();   // g_bnd complete (block-wide global visibility)

    // dedupe: heads + block scan -> uniques + first-occurrence ranks
    int i0 = t * DCH;
    int heads[DCH]; int cnt = 0;
    #pragma unroll
    for (int e = 0; e < DCH; e++) {
        int i = i0 + e; int h = 0;
        if (i < NBND) h = (i == 0) || (g_bnd[i] != g_bnd[i - 1]);
        heads[e] = h; cnt += h;
    }
    sc[t] = cnt; __syncthreads();
    for (int off = 1; off < 1024; off <<= 1) {
        int v = sc[t]; if (t >= off) v += sc[t - off];
        __syncthreads(); sc[t] = v; __syncthreads();
    }
    int excl = sc[t] - cnt;
    int U = sc[1023];
    int u = excl;
    #pragma unroll
    for (int e = 0; e < DCH; e++) {
        int i = i0 + e;
        if (heads[e]) { g_uv[u] = g_bnd[i]; g_pref[u] = (unsigned short)i; u++; }
    }
    if (t == 0) { g_pref[U] = (unsigned short)NBND; g_U = U; }
    __syncthreads();

    // bucket table
    for (int k = t; k <= NBUCK; k += 1024) {
        float edge = fmaf((float)k, BSTEP, BLO);
        int pos = 0, n = U;
        while (n > 0) {
            int half = n >> 1, mid = pos + half;
            if (g_uv[mid] < edge) { pos = mid + 1; n -= half + 1; }
            else                  { n = half; }
        }
        g_bstart[k] = pos;
    }
    __syncthreads();

    // widened max bucket width (must match hist's lo/hi formula)
    int lmax = 0;
    for (int k = t; k < NBUCK; k += 1024) {
        int lo = (k == 0)         ? 0 : g_bstart[k - 1];
        int hi = (k >= NBUCK - 1) ? U : g_bstart[k + 2];
        lmax = max(lmax, hi - lo);
    }
    sc[t] = lmax; __syncthreads();
    for (int off = 512; off > 0; off >>= 1) {
        if (t < off) sc[t] = max(sc[t], sc[t + off]);
        __syncthreads();
    }
    if (t == 0) g_maxw = sc[0];
}

// ---------------------------------------------------------------------------
// K2: histogram (unchanged from R9).
// ---------------------------------------------------------------------------
#define HIST_SMEM (NBND * 4 + (NBND + 2) * 2 + (NBUCK + 1) * 4)   // 54408 B

__global__ void __launch_bounds__(256)
hist_kernel(const float* __restrict__ dm, const int* __restrict__ lengths) {
    extern __shared__ char dyn[];
    float*          suv   = (float*)dyn;                               // [U]
    unsigned short* spref = (unsigned short*)(dyn + NBND * 4);         // [U+1]
    int*            sbst  = (int*)(dyn + NBND * 4 + (NBND + 2) * 2);   // [NBUCK+1]
    int tid = threadIdx.x;

    int U    = g_U;
    int maxw = g_maxw;
    int steps = (maxw > 0) ? (32 - __clz(maxw)) : 0;   // block-uniform

    for (int i = tid; i < U;       i += 256) suv[i]   = g_uv[i];
    for (int i = tid; i <= U;      i += 256) spref[i] = g_pref[i];
    for (int i = tid; i <= NBUCK;  i += 256) sbst[i]  = g_bstart[i];
    __syncthreads();

    for (int task = blockIdx.x; task < NTASK; task += gridDim.x) {
        int b  = task & 31;
        int i0 = (task >> 5) << 2;
        int L  = __ldg(lengths + b);
        if (i0 >= L - 1) continue;

        const float* rowp = dm + ((size_t)b << 16) + ((size_t)i0 << 8) + tid;
        float s[4]; int n[4], pos[4];
        #pragma unroll
        for (int r = 0; r < 4; r++) {
            int i = i0 + r;
            bool valid = (i < L - 1) && (tid > i) && (tid < L);
            float sv = valid ? rowp[r << 8] : 0.0f;
            s[r] = sv;
            int ib = __float2int_rd((sv - BLO) * BINV);
            ib = min(max(ib, 0), NBUCK - 1);
            int lo = (ib == 0)         ? 0 : sbst[ib - 1];
            int hi = (ib >= NBUCK - 1) ? U : sbst[ib + 2];
            pos[r] = lo;
            n[r]   = valid ? (hi - lo) : 0;
        }
        for (int it = 0; it < steps; it++) {
            #pragma unroll
            for (int r = 0; r < 4; r++) {
                if (n[r] > 0) {
                    int half = n[r] >> 1;
                    int mid  = pos[r] + half;
                    if (suv[mid] < s[r]) { pos[r] = mid + 1; n[r] -= half + 1; }
                    else                 { n[r] = half; }
                }
            }
        }
        unsigned long long* hb = g_h + (size_t)b * NSLOT;
        #pragma unroll
        for (int r = 0; r < 4; r++) {
            int i = i0 + r;
            bool valid = (i < L - 1) && (tid > i) && (tid < L);
            if (valid) {
                int pO = spref[pos[r]];
                long long q = (long long)llrintf(s[r] * SCALE_F) + QBIAS;
                atomicAdd(&hb[pO], PACK_ONE + (unsigned long long)q);
            }
        }
    }
}

// ---------------------------------------------------------------------------
// K3: pooled. 1 warp per (batch, segment). Packed 129-cell scan via shuffles,
// range algebra, fixed-point atomics. Self-zeroes each hist cell after read.
// ---------------------------------------------------------------------------
__global__ void __launch_bounds__(POOL_WARPS * 32)
pooled_kernel() {
    __shared__ unsigned long long ps[POOL_WARPS][130];
    int tid = threadIdx.x, warp = tid >> 5, lane = tid & 31;
    int u = blockIdx.x * POOL_WARPS + warp;
    if (u >= NSEG * NB) return;
    int m = u % NSEG;
    int b = u / NSEG;

    unsigned long long* h = g_h + (size_t)b * NSLOT + m * NCELL;
    int base = lane * 4;
    int ncl  = (lane == 31) ? 5 : 4;
    unsigned long long ls[5];
    unsigned long long run = 0ULL;
    #pragma unroll
    for (int e = 0; e < 5; e++) {
        if (e < ncl) {
            ls[e] = run;
            run += __ldcg(h + base + e);
        }
    }
    #pragma unroll
    for (int e = 0; e < 5; e++) {       // restore zero for next graph replay
        if (e < ncl) h[base + e] = 0ULL;
    }
    unsigned long long inc = run;
    #pragma unroll
    for (int off = 1; off < 32; off <<= 1) {
        unsigned long long v = __shfl_up_sync(0xffffffffu, inc, off);
        if (lane >= off) inc += v;
    }
    unsigned long long ex = inc - run;
    #pragma unroll
    for (int e = 0; e < 5; e++) {
        if (e < ncl) ps[warp][base + e] = ex + ls[e];
    }
    if (lane == 31) ps[warp][NCELL] = inc;
    __syncwarp();

    #pragma unroll
    for (int ff = 0; ff < 4; ff++) {
        int f = lane + 32 * ff;
        int idx = m * P2 + f;
        float a = g_A[idx], c = g_Cc[idx];
        int2 rg = g_range[idx];
        unsigned long long dv = ps[warp][rg.y] - ps[warp][rg.x];
        int cnt = (int)(dv >> 48);
        long long sumq = (long long)(dv & LOWMASK) - ((long long)cnt << 29);
        float val = a * (float)((double)sumq * INV_SCALE) + c * (float)cnt;
        long long qq = llrint((double)val * PSCALE);
        atomicAdd(&g_poolq[b * P2 + f], (unsigned long long)qq);
    }
}

// ---------------------------------------------------------------------------
// K4: head. grid NB, 512 threads. Self-zeroes g_poolq after reading.
// ---------------------------------------------------------------------------
__global__ void __launch_bounds__(512)
head_kernel(const float* __restrict__ W3, const float* __restrict__ b3,
            const float* __restrict__ W4, const float* __restrict__ b4,
            const float* __restrict__ W5, const float* __restrict__ b5,
            float* __restrict__ out) {
    __shared__ float pooled[P2];
    __shared__ float r1v[R1];
    __shared__ float r2v[R2];
    __shared__ float part[512];
    int b = blockIdx.x, t = threadIdx.x;

    if (t < P2) {
        pooled[t] = (float)((double)(long long)g_poolq[b * P2 + t] * INV_PSCALE);
        g_poolq[b * P2 + t] = 0ULL;     // restore zero for next graph replay
    }
    __syncthreads();

    {   // layer1: 256 outputs, 2-way K split (K=128)
        int o = t & 255, h = t >> 8;
        float v = 0.0f;
        int k0 = h * 64;
        #pragma unroll
        for (int k = 0; k < 64; k++)
            v = fmaf(pooled[k0 + k], W3[(k0 + k) * R1 + o], v);
        part[t] = v;
    }
    __syncthreads();
    if (t < R1)
        r1v[t] = fmaxf(b3[t] + part[t] + part[t + 256], 0.0f);
    __syncthreads();

    {   // layer2: 128 outputs, 4-way K split (K=256)
        int o = t & 127, ch = t >> 7;
        float v = 0.0f;
        int k0 = ch * 64;
        #pragma unroll
        for (int k = 0; k < 64; k++)
            v = fmaf(r1v[k0 + k], W4[(k0 + k) * R2 + o], v);
        __syncthreads();
        part[t] = v;
    }
    __syncthreads();
    if (t < R2) {
        float v = b4[t];
        #pragma unroll
        for (int j = 0; j < 4; j++) v += part[t + 128 * j];
        r2v[t] = fmaxf(v, 0.0f);
    }
    __syncthreads();

    {   // layer3: 64 outputs, 8-way K split (K=128)
        int o = t & 63, ch = t >> 6;
        float v = 0.0f;
        int k0 = ch * 16;
        #pragma unroll
        for (int k = 0; k < 16; k++)
            v = fmaf(r2v[k0 + k], W5[(k0 + k) * OD + o], v);
        __syncthreads();
        part[t] = v;
    }
    __syncthreads();
    if (t < OD) {
        float v = b5[t];
        #pragma unroll
        for (int j = 0; j < 8; j++) v += part[t + 64 * j];
        out[b * OD + t] = v;
    }
}

// ---------------------------------------------------------------------------
extern "C" void kernel_launch(void* const* d_in, const int* in_sizes, int n_in,
                              void* d_out, int out_size) {
    const float* dm      = (const float*)d_in[0];
    const int*   lengths = (const int*)  d_in[1];
    const float* W1 = (const float*)d_in[2],  *b1 = (const float*)d_in[3];
    const float* W2 = (const float*)d_in[4],  *b2 = (const float*)d_in[5];
    const float* W3 = (const float*)d_in[6],  *b3 = (const float*)d_in[7];
    const float* W4 = (const float*)d_in[8],  *b4 = (const float*)d_in[9];
    const float* W5 = (const float*)d_in[10], *b5 = (const float*)d_in[11];
    float* out = (float*)d_out;

    cudaFuncSetAttribute((const void*)hist_kernel,
                         cudaFuncAttributeMaxDynamicSharedMemorySize, HIST_SMEM);

    const int pool_grid = (NSEG * NB + POOL_WARPS - 1) / POOL_WARPS;  // 260

    prep_kernel<<<1, 1024>>>(W1, b1, W2, b2);
    hist_kernel<<<HIST_GRID, 256, HIST_SMEM>>>(dm, lengths);
    pooled_kernel<<<pool_grid, POOL_WARPS * 32>>>();
    head_kernel<<<NB, 512>>>(W3, b3, W4, b4, W5, b5, out);
}

// round 12
// speedup vs baseline: 2.2319x; 2.2200x over previous
#include <cuda_runtime.h>
#include <math_constants.h>

// ScalarDistanceDeepSet via exact piecewise-linear collapse + cell histogram.
// setup (65 table blocks + L2-warm blocks; NO zero pass), dedupe (1 block:
// uniques + rank map + bucket index), hist (bucketed short search -> packed
// 64-bit atomic), pooled (warp per (batch,segment), self-zeroes hist cells),
// head (small MLP, self-zeroes pooled accumulators).
// Device globals start zero (.bss); every consumer restores zero after reading
// so each graph replay starts clean. All cross-block accumulation is integer.

#define NB    32
#define NN    256
#define P1    64
#define P2    128
#define R1    256
#define R2    128
#define OD    64
#define NSEG  65
#define NCELL 129
#define NSLOT (NSEG * NCELL)      // 8385
#define NBND  (NSLOT - 1)         // 8384
#define SCALE_F    67108864.0f    // 2^26
#define INV_SCALE  (1.0 / 67108864.0)
#define PSCALE     4194304.0      // 2^22
#define INV_PSCALE (1.0 / 4194304.0)
#define QBIAS      (1LL << 29)
#define PACK_ONE   (1ULL << 48)
#define LOWMASK    ((1ULL << 48) - 1ULL)
#define NBUCK 1024
#define BLO   (-6.0f)
#define BSTEP (12.0f / 1024.0f)
#define BINV  (1024.0f / 12.0f)
#define HIST_GRID 592
#define NTASK (NB * (NN / 4))     // 2048
#define POOL_WARPS 8
#define SETUP_GRID 96             // 65 tables + 31 warm

__device__ float              g_bnd[NBND];
__device__ float              g_A[NSEG * P2];
__device__ float              g_Cc[NSEG * P2];
__device__ int2               g_range[NSEG * P2];
__device__ float              g_uv[NBND];           // unique sorted boundaries
__device__ unsigned short     g_pref[NBND + 1];     // first-occurrence rank
__device__ int                g_bstart[NBUCK + 1];  // count(uv < edge_k)
__device__ int                g_U;
__device__ int                g_maxw;
__device__ unsigned long long g_h[NB * NSLOT];      // packed (cnt<<48 | q+bias)
__device__ unsigned long long g_poolq[NB * P2];     // fixed-point pooled
__device__ float              g_sink[256];

// ---------------------------------------------------------------------------
// Setup: blocks 0..64 build tables for segment m (block-local ranks);
// blocks >=65 stream head weights into L2. No zeroing (self-zero scheme).
// ---------------------------------------------------------------------------
__global__ void __launch_bounds__(256)
setup_kernel(const float* __restrict__ W1, const float* __restrict__ b1,
             const float* __restrict__ W2, const float* __restrict__ b2,
             const float* __restrict__ W3, const float* __restrict__ W4,
             const float* __restrict__ W5) {
    __shared__ float sw[P1], sbb[P1], stk[P1], sts[P1], sth[P2];
    __shared__ int   srk[P1];
    int tid = threadIdx.x;
    int m = blockIdx.x;

    if (m >= NSEG) {
        float acc = 0.0f;
        int idx0 = (m - NSEG) * 256 + tid;
        int stride = (SETUP_GRID - NSEG) * 256;
        for (int i = idx0; i < P2 * R1; i += stride) acc += W3[i];
        for (int i = idx0; i < R1 * R2; i += stride) acc += W4[i];
        for (int i = idx0; i < R2 * OD; i += stride) acc += W5[i];
        if (tid == 0) g_sink[m - NSEG] = acc;
        return;
    }

    if (tid < P1) {
        float w = W1[tid], b = b1[tid];
        sw[tid] = w; sbb[tid] = b;
        stk[tid] = (w != 0.0f) ? (-b / w) : CUDART_INF_F;
    }
    __syncthreads();
    if (tid < P1) {
        float tkv = stk[tid];
        int r = 0;
        for (int kk = 0; kk < P1; kk++) {
            float tv = stk[kk];
            if (tv < tkv || (tv == tkv && kk < tid)) r++;
        }
        srk[tid] = r;
        sts[r] = tkv;
    }
    __syncthreads();
    if (tid < P2) {
        float a = 0.0f, c = b2[tid];
        for (int k = 0; k < P1; k++) {
            float w = sw[k], b = sbb[k];
            int r = srk[k];
            bool active = (w > 0.0f) ? (m > r)
                        : (w < 0.0f) ? (m <= r)
                        : (b > 0.0f);
            if (active) {
                float w2 = W2[k * P2 + tid];
                a = fmaf(w, w2, a);
                c = fmaf(b, w2, c);
            }
        }
        int idx = m * P2 + tid;
        g_A[idx] = a; g_Cc[idx] = c;

        float lo_t = (m == 0)        ? -CUDART_INF_F : sts[m - 1];
        float hi_t = (m == NSEG - 1) ?  CUDART_INF_F : sts[m];
        float th;
        if (a != 0.0f) th = fminf(fmaxf(-c / a, lo_t), hi_t);
        else           th = lo_t;
        sth[tid] = th;
    }
    __syncthreads();
    if (tid < P2) {
        int idx = m * P2 + tid;
        float a = g_A[idx], c = g_Cc[idx];
        float th = sth[tid];
        int p = 0;
        for (int k = 0; k < P2; k++) {
            float tv = sth[k];
            if (tv < th || (tv == th && k < tid)) p++;
        }
        g_bnd[m * NCELL + p] = th;
        if (tid == 0 && m < NSEG - 1) g_bnd[m * NCELL + P2] = sts[m];
        int rlo, rhi;
        if (a > 0.0f)      { rlo = p + 1; rhi = NCELL; }
        else if (a < 0.0f) { rlo = 0;     rhi = p + 1; }
        else               { rlo = 0;     rhi = (c > 0.0f) ? NCELL : 0; }
        g_range[idx] = make_int2(rlo, rhi);
    }
}

// ---------------------------------------------------------------------------
// Dedupe: single block. g_bnd is globally sorted by construction; mark heads,
// block scan -> unique array uv + first-occurrence ranks pref, then bucket
// table bstart and the widened max bucket width (uniform search step count).
// ---------------------------------------------------------------------------
#define DCH 9   // 1024*9 >= 8384
__global__ void __launch_bounds__(1024)
dedupe_kernel() {
    __shared__ int sc[1024];
    int t = threadIdx.x;
    int i0 = t * DCH;
    int heads[DCH]; int cnt = 0;
    #pragma unroll
    for (int e = 0; e < DCH; e++) {
        int i = i0 + e; int h = 0;
        if (i < NBND) h = (i == 0) || (g_bnd[i] != g_bnd[i - 1]);
        heads[e] = h; cnt += h;
    }
    sc[t] = cnt; __syncthreads();
    for (int off = 1; off < 1024; off <<= 1) {
        int v = sc[t]; if (t >= off) v += sc[t - off];
        __syncthreads(); sc[t] = v; __syncthreads();
    }
    int excl = sc[t] - cnt;
    int U = sc[1023];
    int u = excl;
    #pragma unroll
    for (int e = 0; e < DCH; e++) {
        int i = i0 + e;
        if (heads[e]) { g_uv[u] = g_bnd[i]; g_pref[u] = (unsigned short)i; u++; }
    }
    if (t == 0) { g_pref[U] = (unsigned short)NBND; g_U = U; }
    __threadfence();
    __syncthreads();

    // bucket table: bstart[k] = count(uv < BLO + k*BSTEP)
    for (int k = t; k <= NBUCK; k += 1024) {
        float edge = fmaf((float)k, BSTEP, BLO);
        int pos = 0, n = U;
        while (n > 0) {
            int half = n >> 1, mid = pos + half;
            if (g_uv[mid] < edge) { pos = mid + 1; n -= half + 1; }
            else                  { n = half; }
        }
        g_bstart[k] = pos;
    }
    __threadfence();
    __syncthreads();

    // widened max bucket width (must match hist's lo/hi formula exactly)
    int lmax = 0;
    for (int k = t; k < NBUCK; k += 1024) {
        int lo = (k == 0)         ? 0 : g_bstart[k - 1];
        int hi = (k >= NBUCK - 1) ? U : g_bstart[k + 2];
        lmax = max(lmax, hi - lo);
    }
    sc[t] = lmax; __syncthreads();
    for (int off = 512; off > 0; off >>= 1) {
        if (t < off) sc[t] = max(sc[t], sc[t + off]);
        __syncthreads();
    }
    if (t == 0) g_maxw = sc[0];
}

// ---------------------------------------------------------------------------
// Histogram: per pair, bucket -> short uniform-step branchless search over
// uniques (ILP-4 across rows) -> original rank via pref -> one packed atomic.
// ---------------------------------------------------------------------------
#define HIST_SMEM (NBND * 4 + (NBND + 2) * 2 + (NBUCK + 1) * 4)   // 54408 B

__global__ void __launch_bounds__(256)
hist_kernel(const float* __restrict__ dm, const int* __restrict__ lengths) {
    extern __shared__ char dyn[];
    float*          suv   = (float*)dyn;                               // [U]
    unsigned short* spref = (unsigned short*)(dyn + NBND * 4);         // [U+1]
    int*            sbst  = (int*)(dyn + NBND * 4 + (NBND + 2) * 2);   // [NBUCK+1]
    int tid = threadIdx.x;

    int U    = g_U;
    int maxw = g_maxw;
    int steps = (maxw > 0) ? (32 - __clz(maxw)) : 0;   // block-uniform

    for (int i = tid; i < U;       i += 256) suv[i]   = g_uv[i];
    for (int i = tid; i <= U;      i += 256) spref[i] = g_pref[i];
    for (int i = tid; i <= NBUCK;  i += 256) sbst[i]  = g_bstart[i];
    __syncthreads();

    for (int task = blockIdx.x; task < NTASK; task += gridDim.x) {
        int b  = task & 31;
        int i0 = (task >> 5) << 2;
        int L  = __ldg(lengths + b);
        if (i0 >= L - 1) continue;

        const float* rowp = dm + ((size_t)b << 16) + ((size_t)i0 << 8) + tid;
        float s[4]; int n[4], pos[4];
        #pragma unroll
        for (int r = 0; r < 4; r++) {
            int i = i0 + r;
            bool valid = (i < L - 1) && (tid > i) && (tid < L);
            float sv = valid ? rowp[r << 8] : 0.0f;
            s[r] = sv;
            int ib = __float2int_rd((sv - BLO) * BINV);
            ib = min(max(ib, 0), NBUCK - 1);
            int lo = (ib == 0)         ? 0 : sbst[ib - 1];
            int hi = (ib >= NBUCK - 1) ? U : sbst[ib + 2];
            pos[r] = lo;
            n[r]   = valid ? (hi - lo) : 0;
        }
        for (int it = 0; it < steps; it++) {
            #pragma unroll
            for (int r = 0; r < 4; r++) {
                if (n[r] > 0) {
                    int half = n[r] >> 1;
                    int mid  = pos[r] + half;
                    if (suv[mid] < s[r]) { pos[r] = mid + 1; n[r] -= half + 1; }
                    else                 { n[r] = half; }
                }
            }
        }
        unsigned long long* hb = g_h + (size_t)b * NSLOT;
        #pragma unroll
        for (int r = 0; r < 4; r++) {
            int i = i0 + r;
            bool valid = (i < L - 1) && (tid > i) && (tid < L);
            if (valid) {
                int pO = spref[pos[r]];
                long long q = (long long)llrintf(s[r] * SCALE_F) + QBIAS;
                atomicAdd(&hb[pO], PACK_ONE + (unsigned long long)q);
            }
        }
    }
}

// ---------------------------------------------------------------------------
// Pooled: 1 warp per (batch, segment). Packed 129-cell scan via shuffles,
// range algebra, fixed-point atomics. Self-zeroes each hist cell after read.
// ---------------------------------------------------------------------------
__global__ void __launch_bounds__(POOL_WARPS * 32)
pooled_kernel() {
    __shared__ unsigned long long ps[POOL_WARPS][130];
    int tid = threadIdx.x, warp = tid >> 5, lane = tid & 31;
    int u = blockIdx.x * POOL_WARPS + warp;
    if (u >= NSEG * NB) return;
    int m = u % NSEG;
    int b = u / NSEG;

    unsigned long long* h = g_h + (size_t)b * NSLOT + m * NCELL;
    int base = lane * 4;
    int ncl  = (lane == 31) ? 5 : 4;
    unsigned long long ls[5];
    unsigned long long run = 0ULL;
    #pragma unroll
    for (int e = 0; e < 5; e++) {
        if (e < ncl) {
            ls[e] = run;
            run += __ldcg(h + base + e);
        }
    }
    #pragma unroll
    for (int e = 0; e < 5; e++) {       // restore zero for next graph replay
        if (e < ncl) h[base + e] = 0ULL;
    }
    unsigned long long inc = run;
    #pragma unroll
    for (int off = 1; off < 32; off <<= 1) {
        unsigned long long v = __shfl_up_sync(0xffffffffu, inc, off);
        if (lane >= off) inc += v;
    }
    unsigned long long ex = inc - run;
    #pragma unroll
    for (int e = 0; e < 5; e++) {
        if (e < ncl) ps[warp][base + e] = ex + ls[e];
    }
    if (lane == 31) ps[warp][NCELL] = inc;
    __syncwarp();

    #pragma unroll
    for (int ff = 0; ff < 4; ff++) {
        int f = lane + 32 * ff;
        int idx = m * P2 + f;
        float a = g_A[idx], c = g_Cc[idx];
        int2 rg = g_range[idx];
        unsigned long long dv = ps[warp][rg.y] - ps[warp][rg.x];
        int cnt = (int)(dv >> 48);
        long long sumq = (long long)(dv & LOWMASK) - ((long long)cnt << 29);
        float val = a * (float)((double)sumq * INV_SCALE) + c * (float)cnt;
        long long qq = llrint((double)val * PSCALE);
        atomicAdd(&g_poolq[b * P2 + f], (unsigned long long)qq);
    }
}

// ---------------------------------------------------------------------------
// Head: grid NB, 512 threads. Self-zeroes g_poolq after reading.
// ---------------------------------------------------------------------------
__global__ void __launch_bounds__(512)
head_kernel(const float* __restrict__ W3, const float* __restrict__ b3,
            const float* __restrict__ W4, const float* __restrict__ b4,
            const float* __restrict__ W5, const float* __restrict__ b5,
            float* __restrict__ out) {
    __shared__ float pooled[P2];
    __shared__ float r1v[R1];
    __shared__ float r2v[R2];
    __shared__ float part[512];
    int b = blockIdx.x, t = threadIdx.x;

    if (t < P2) {
        pooled[t] = (float)((double)(long long)g_poolq[b * P2 + t] * INV_PSCALE);
        g_poolq[b * P2 + t] = 0ULL;     // restore zero for next graph replay
    }
    __syncthreads();

    {   // layer1: 256 outputs, 2-way K split (K=128)
        int o = t & 255, h = t >> 8;
        float v = 0.0f;
        int k0 = h * 64;
        #pragma unroll
        for (int k = 0; k < 64; k++)
            v = fmaf(pooled[k0 + k], W3[(k0 + k) * R1 + o], v);
        part[t] = v;
    }
    __syncthreads();
    if (t < R1)
        r1v[t] = fmaxf(b3[t] + part[t] + part[t + 256], 0.0f);
    __syncthreads();

    {   // layer2: 128 outputs, 4-way K split (K=256)
        int o = t & 127, ch = t >> 7;
        float v = 0.0f;
        int k0 = ch * 64;
        #pragma unroll
        for (int k = 0; k < 64; k++)
            v = fmaf(r1v[k0 + k], W4[(k0 + k) * R2 + o], v);
        __syncthreads();
        part[t] = v;
    }
    __syncthreads();
    if (t < R2) {
        float v = b4[t];
        #pragma unroll
        for (int j = 0; j < 4; j++) v += part[t + 128 * j];
        r2v[t] = fmaxf(v, 0.0f);
    }
    __syncthreads();

    {   // layer3: 64 outputs, 8-way K split (K=128)
        int o = t & 63, ch = t >> 6;
        float v = 0.0f;
        int k0 = ch * 16;
        #pragma unroll
        for (int k = 0; k < 16; k++)
            v = fmaf(r2v[k0 + k], W5[(k0 + k) * OD + o], v);
        __syncthreads();
        part[t] = v;
    }
    __syncthreads();
    if (t < OD) {
        float v = b5[t];
        #pragma unroll
        for (int j = 0; j < 8; j++) v += part[t + 64 * j];
        out[b * OD + t] = v;
    }
}

// ---------------------------------------------------------------------------
extern "C" void kernel_launch(void* const* d_in, const int* in_sizes, int n_in,
                              void* d_out, int out_size) {
    const float* dm      = (const float*)d_in[0];
    const int*   lengths = (const int*)  d_in[1];
    const float* W1 = (const float*)d_in[2],  *b1 = (const float*)d_in[3];
    const float* W2 = (const float*)d_in[4],  *b2 = (const float*)d_in[5];
    const float* W3 = (const float*)d_in[6],  *b3 = (const float*)d_in[7];
    const float* W4 = (const float*)d_in[8],  *b4 = (const float*)d_in[9];
    const float* W5 = (const float*)d_in[10], *b5 = (const float*)d_in[11];
    float* out = (float*)d_out;

    cudaFuncSetAttribute((const void*)hist_kernel,
                         cudaFuncAttributeMaxDynamicSharedMemorySize, HIST_SMEM);

    const int pool_grid = (NSEG * NB + POOL_WARPS - 1) / POOL_WARPS;  // 260

    setup_kernel<<<SETUP_GRID, 256>>>(W1, b1, W2, b2, W3, W4, W5);
    dedupe_kernel<<<1, 1024>>>();
    hist_kernel<<<HIST_GRID, 256, HIST_SMEM>>>(dm, lengths);
    pooled_kernel<<<pool_grid, POOL_WARPS * 32>>>();
    head_kernel<<<NB, 512>>>(W3, b3, W4, b4, W5, b5, out);
}